// round 12
// baseline (speedup 1.0000x reference)
#include <cuda_runtime.h>
#include <cuda_bf16.h>
#include <mma.h>
#include <cstdint>
#include <math.h>

#define VOCAB   100000
#define EMBED   64
#define SENT    20
#define MEM     50
#define BATCH   32
#define HOPS    3

// Scratch: 4 context tensors [B,M,E] (mA, mC0, mC1, mC2) + final u [B,E]
__device__ float g_m[4][BATCH * MEM * EMBED];   // 1.6 MB
__device__ float g_u[BATCH * EMBED];

__device__ __forceinline__ uint32_t pack_bf16x2(float x, float y) {
    __nv_bfloat162 t = __floats2bfloat162_rn(x, y);
    return *reinterpret_cast<uint32_t*>(&t);
}

// ---------------------------------------------------------------------------
// Kernel A: gather + position-encode the 4 context tensors.
// float4 gathers: block = 256 thr = 4 (b,m) pairs x 4 tables x 16 thr (4 dims
// each). Same ~20-deep MLP per thread but 4x bytes in flight per warp.
// ---------------------------------------------------------------------------
__global__ void __launch_bounds__(256) context_kernel(
        const int* __restrict__ stories,
        const float* __restrict__ A,
        const float* __restrict__ C,
        const float* __restrict__ enc) {
    int sub = threadIdx.x >> 6;          // (b,m) pair within block: 0..3
    int bm  = blockIdx.x * 4 + sub;      // 0..1599
    int t   = (threadIdx.x >> 4) & 3;    // table 0..3
    int eg  = threadIdx.x & 15;          // float4 group (dims 4*eg..4*eg+3)

    __shared__ int s_idx[4][SENT];
    if (threadIdx.x < 4 * SENT)
        s_idx[threadIdx.x / SENT][threadIdx.x % SENT] =
            stories[blockIdx.x * 4 * SENT + threadIdx.x];
    __syncthreads();

    const float4* tab4 = (t == 0) ? (const float4*)A
                                  : (const float4*)(C + (size_t)(t - 1) * VOCAB * EMBED);
    const float4* enc4 = (const float4*)enc;

    float4 acc = make_float4(0.f, 0.f, 0.f, 0.f);
#pragma unroll
    for (int s = 0; s < SENT; s++) {
        int idx  = s_idx[sub][s];
        float4 v = __ldg(tab4 + (size_t)idx * (EMBED / 4) + eg);
        float4 e = enc4[s * (EMBED / 4) + eg];
        acc.x = fmaf(v.x, e.x, acc.x);
        acc.y = fmaf(v.y, e.y, acc.y);
        acc.z = fmaf(v.z, e.z, acc.z);
        acc.w = fmaf(v.w, e.w, acc.w);
    }
    *(float4*)&g_m[t][bm * EMBED + eg * 4] = acc;
}

// ---------------------------------------------------------------------------
// Kernel B: query embedding + 3-hop attention. (round-5 version, ~3us)
// ---------------------------------------------------------------------------
__global__ void __launch_bounds__(64) hops_kernel(
        const int* __restrict__ queries,
        const float* __restrict__ A,
        const float* __restrict__ enc) {
    int b    = blockIdx.x;
    int tid  = threadIdx.x;
    int lane = tid & 31;
    int wid  = tid >> 5;

    __shared__ float s_u[EMBED];
    __shared__ float s_p[EMBED];
    __shared__ float s_red[2];
    __shared__ float s_inv;

    int qidx[SENT];
#pragma unroll
    for (int s = 0; s < SENT; s++) qidx[s] = queries[b * SENT + s];
    float ue = 0.f;
#pragma unroll
    for (int s = 0; s < SENT; s++)
        ue = fmaf(__ldg(A + (size_t)qidx[s] * EMBED + tid), enc[s * EMBED + tid], ue);
    s_u[tid] = ue;
    __syncthreads();

    for (int hop = 0; hop < HOPS; hop++) {
        const float* mX = g_m[hop]     + b * MEM * EMBED;
        const float* cX = g_m[hop + 1] + b * MEM * EMBED;

        float d = -1e30f;
        if (tid < MEM) {
            float acc = 0.f;
#pragma unroll 16
            for (int e = 0; e < EMBED; e++)
                acc = fmaf(mX[tid * EMBED + e], s_u[e], acc);
            d = acc;
        }

        float w = d;
#pragma unroll
        for (int off = 16; off > 0; off >>= 1)
            w = fmaxf(w, __shfl_xor_sync(0xffffffffu, w, off));
        if (lane == 0) s_red[wid] = w;
        __syncthreads();
        float mx = fmaxf(s_red[0], s_red[1]);

        float p = (tid < MEM) ? __expf(d - mx) : 0.f;
        s_p[tid] = p;
        float sw = p;
#pragma unroll
        for (int off = 16; off > 0; off >>= 1)
            sw += __shfl_xor_sync(0xffffffffu, sw, off);
        if (lane == 0) s_red[wid] = sw;
        __syncthreads();
        if (tid == 0) s_inv = 1.f / (s_red[0] + s_red[1]);
        __syncthreads();

        float inv = s_inv;
        float o = 0.f;
#pragma unroll 10
        for (int m = 0; m < MEM; m++)
            o = fmaf(s_p[m] * inv, cX[m * EMBED + tid], o);
        float nu = s_u[tid] + o;
        __syncthreads();
        s_u[tid] = nu;
        __syncthreads();
    }
    g_u[b * EMBED + tid] = s_u[tid];
}

// ---------------------------------------------------------------------------
// Kernel C: out[32, V] = u[32,64] @ C2[V,64]^T via wmma bf16 (HMMA —
// baseline PTX, assembles for plain sm_103 unlike tcgen05).
// Per 64-row tile: fp32 -> bf16 hi/lo in smem, then per (m,n) tile
//   D = Ah*Bh + Al*Bh + Ah*Bl   (fp32 accumulate; dropped Al*Bl <= 2^-18)
// Output written transposed via store_matrix_sync(mem_col_major, ldm=VOCAB).
// Memory-bound: 25.6MB read + 12.8MB write.
// ---------------------------------------------------------------------------
#define GTILE 64
#define LDA   80      // padded stride (elements): 160B rows, 16B-aligned

struct __align__(16) GemmSmem {
    __nv_bfloat16 a_hi[GTILE * LDA];   // 10 KB
    __nv_bfloat16 a_lo[GTILE * LDA];   // 10 KB
    __nv_bfloat16 b_hi[BATCH * LDA];   //  5 KB
    __nv_bfloat16 b_lo[BATCH * LDA];   //  5 KB
};

__global__ void __launch_bounds__(128) out_gemm_wmma(
        const float* __restrict__ C2, float* __restrict__ out) {
    using namespace nvcuda;
    __shared__ GemmSmem sm;
    int tid = threadIdx.x;
    int v0  = blockIdx.x * GTILE;

    // ---- fp32 -> bf16 hi/lo conversion into smem ----
    if (tid < GTILE) {                         // A rows: C2[v0+tid]
        int r = tid;
        bool valid = (v0 + r) < VOCAB;
        const float4* src = (const float4*)(C2 + (size_t)(v0 + r) * EMBED);
#pragma unroll
        for (int ch = 0; ch < 8; ch++) {
            float f[8];
            if (valid) {
                float4 f0 = __ldg(src + 2 * ch), f1 = __ldg(src + 2 * ch + 1);
                f[0]=f0.x; f[1]=f0.y; f[2]=f0.z; f[3]=f0.w;
                f[4]=f1.x; f[5]=f1.y; f[6]=f1.z; f[7]=f1.w;
            } else {
#pragma unroll
                for (int i = 0; i < 8; i++) f[i] = 0.f;
            }
            float h[8], l[8];
#pragma unroll
            for (int i = 0; i < 8; i++) {
                h[i] = __bfloat162float(__float2bfloat16_rn(f[i]));
                l[i] = f[i] - h[i];
            }
            uint4 hw = make_uint4(pack_bf16x2(h[0],h[1]), pack_bf16x2(h[2],h[3]),
                                  pack_bf16x2(h[4],h[5]), pack_bf16x2(h[6],h[7]));
            uint4 lw = make_uint4(pack_bf16x2(l[0],l[1]), pack_bf16x2(l[2],l[3]),
                                  pack_bf16x2(l[4],l[5]), pack_bf16x2(l[6],l[7]));
            *(uint4*)&sm.a_hi[r * LDA + ch * 8] = hw;
            *(uint4*)&sm.a_lo[r * LDA + ch * 8] = lw;
        }
    } else if (tid < GTILE + BATCH) {          // B rows: u[tid-GTILE]
        int n = tid - GTILE;
        const float4* src = (const float4*)(g_u + n * EMBED);
#pragma unroll
        for (int ch = 0; ch < 8; ch++) {
            float4 f0 = src[2 * ch], f1 = src[2 * ch + 1];
            float f[8] = {f0.x, f0.y, f0.z, f0.w, f1.x, f1.y, f1.z, f1.w};
            float h[8], l[8];
#pragma unroll
            for (int i = 0; i < 8; i++) {
                h[i] = __bfloat162float(__float2bfloat16_rn(f[i]));
                l[i] = f[i] - h[i];
            }
            uint4 hw = make_uint4(pack_bf16x2(h[0],h[1]), pack_bf16x2(h[2],h[3]),
                                  pack_bf16x2(h[4],h[5]), pack_bf16x2(h[6],h[7]));
            uint4 lw = make_uint4(pack_bf16x2(l[0],l[1]), pack_bf16x2(l[2],l[3]),
                                  pack_bf16x2(l[4],l[5]), pack_bf16x2(l[6],l[7]));
            *(uint4*)&sm.b_hi[n * LDA + ch * 8] = hw;
            *(uint4*)&sm.b_lo[n * LDA + ch * 8] = lw;
        }
    }
    __syncthreads();

    // ---- wmma: warp w owns m-tile rows [w*16, w*16+16), both n-tiles ----
    int wid = tid >> 5;
    int m0  = wid * 16;

    wmma::fragment<wmma::accumulator, 16, 16, 16, float> d0, d1;
    wmma::fill_fragment(d0, 0.f);
    wmma::fill_fragment(d1, 0.f);
    wmma::fragment<wmma::matrix_a, 16, 16, 16, __nv_bfloat16, wmma::row_major> ah, al;
    wmma::fragment<wmma::matrix_b, 16, 16, 16, __nv_bfloat16, wmma::col_major> bh0, bh1, bl0, bl1;

#pragma unroll
    for (int k = 0; k < 4; k++) {
        wmma::load_matrix_sync(ah,  &sm.a_hi[m0 * LDA + k * 16], LDA);
        wmma::load_matrix_sync(al,  &sm.a_lo[m0 * LDA + k * 16], LDA);
        wmma::load_matrix_sync(bh0, &sm.b_hi[ 0 * LDA + k * 16], LDA);
        wmma::load_matrix_sync(bh1, &sm.b_hi[16 * LDA + k * 16], LDA);
        wmma::load_matrix_sync(bl0, &sm.b_lo[ 0 * LDA + k * 16], LDA);
        wmma::load_matrix_sync(bl1, &sm.b_lo[16 * LDA + k * 16], LDA);
        wmma::mma_sync(d0, ah, bh0, d0);
        wmma::mma_sync(d0, al, bh0, d0);
        wmma::mma_sync(d0, ah, bl0, d0);
        wmma::mma_sync(d1, ah, bh1, d1);
        wmma::mma_sync(d1, al, bh1, d1);
        wmma::mma_sync(d1, ah, bl1, d1);
    }

    // D element (m,n) -> out[n * VOCAB + v] : column-major with ldm = VOCAB.
    // VOCAB % 16 == 0, so each 16-row m-tile is fully valid or fully invalid.
    int vt = v0 + m0;
    if (vt + 16 <= VOCAB) {
        wmma::store_matrix_sync(out + vt,                      d0, VOCAB, wmma::mem_col_major);
        wmma::store_matrix_sync(out + (size_t)16 * VOCAB + vt, d1, VOCAB, wmma::mem_col_major);
    }
}

// ---------------------------------------------------------------------------
extern "C" void kernel_launch(void* const* d_in, const int* in_sizes, int n_in,
                              void* d_out, int out_size) {
    const int*   stories = (const int*)d_in[0];
    const int*   queries = (const int*)d_in[1];
    const float* A       = (const float*)d_in[2];
    const float* C       = (const float*)d_in[3];
    const float* enc     = (const float*)d_in[4];
    float*       out     = (float*)d_out;

    context_kernel<<<BATCH * MEM / 4, 256>>>(stories, A, C, enc);
    hops_kernel<<<BATCH, 64>>>(queries, A, enc);
    out_gemm_wmma<<<(VOCAB + GTILE - 1) / GTILE, 128>>>(
        C + (size_t)2 * VOCAB * EMBED, out);
}

// round 14
// speedup vs baseline: 1.4378x; 1.4378x over previous
#include <cuda_runtime.h>
#include <cuda_bf16.h>
#include <mma.h>
#include <cstdint>
#include <math.h>

#define VOCAB   100000
#define EMBED   64
#define SENT    20
#define MEM     50
#define BATCH   32
#define HOPS    3

// Scratch: 4 context tensors [B,M,E] (mA, mC0, mC1, mC2) + final u [B,E]
__device__ float g_m[4][BATCH * MEM * EMBED];   // 1.6 MB
__device__ float g_u[BATCH * EMBED];

__device__ __forceinline__ uint32_t pack_bf16x2(float x, float y) {
    __nv_bfloat162 t = __floats2bfloat162_rn(x, y);
    return *reinterpret_cast<uint32_t*>(&t);
}

// ---------------------------------------------------------------------------
// Kernel A: gather + position-encode the 4 context tensors.
// Round-5 version (scalar gathers, 4 tables x 64 dims, 1600 blocks):
// measured 10.2-10.4us, 78% occ across three runs.
// ---------------------------------------------------------------------------
__global__ void __launch_bounds__(256) context_kernel(
        const int* __restrict__ stories,
        const float* __restrict__ A,
        const float* __restrict__ C,
        const float* __restrict__ enc) {
    int bm = blockIdx.x;           // 0..1599
    int t  = threadIdx.x >> 6;     // table 0..3
    int e  = threadIdx.x & 63;     // embed dim

    __shared__ int s_idx[SENT];
    if (threadIdx.x < SENT) s_idx[threadIdx.x] = stories[bm * SENT + threadIdx.x];
    __syncthreads();

    const float* tab = (t == 0) ? A : (C + (size_t)(t - 1) * VOCAB * EMBED);

    float vals[SENT];
#pragma unroll
    for (int s = 0; s < SENT; s++)
        vals[s] = __ldg(tab + (size_t)s_idx[s] * EMBED + e);

    float acc = 0.f;
#pragma unroll
    for (int s = 0; s < SENT; s++)
        acc = fmaf(vals[s], enc[s * EMBED + e], acc);

    g_m[t][bm * EMBED + e] = acc;
}

// ---------------------------------------------------------------------------
// Kernel B: query embedding + 3-hop attention. (round-5 version, ~3us)
// ---------------------------------------------------------------------------
__global__ void __launch_bounds__(64) hops_kernel(
        const int* __restrict__ queries,
        const float* __restrict__ A,
        const float* __restrict__ enc) {
    int b    = blockIdx.x;
    int tid  = threadIdx.x;
    int lane = tid & 31;
    int wid  = tid >> 5;

    __shared__ float s_u[EMBED];
    __shared__ float s_p[EMBED];
    __shared__ float s_red[2];
    __shared__ float s_inv;

    int qidx[SENT];
#pragma unroll
    for (int s = 0; s < SENT; s++) qidx[s] = queries[b * SENT + s];
    float ue = 0.f;
#pragma unroll
    for (int s = 0; s < SENT; s++)
        ue = fmaf(__ldg(A + (size_t)qidx[s] * EMBED + tid), enc[s * EMBED + tid], ue);
    s_u[tid] = ue;
    __syncthreads();

    for (int hop = 0; hop < HOPS; hop++) {
        const float* mX = g_m[hop]     + b * MEM * EMBED;
        const float* cX = g_m[hop + 1] + b * MEM * EMBED;

        float d = -1e30f;
        if (tid < MEM) {
            float acc = 0.f;
#pragma unroll 16
            for (int e = 0; e < EMBED; e++)
                acc = fmaf(mX[tid * EMBED + e], s_u[e], acc);
            d = acc;
        }

        float w = d;
#pragma unroll
        for (int off = 16; off > 0; off >>= 1)
            w = fmaxf(w, __shfl_xor_sync(0xffffffffu, w, off));
        if (lane == 0) s_red[wid] = w;
        __syncthreads();
        float mx = fmaxf(s_red[0], s_red[1]);

        float p = (tid < MEM) ? __expf(d - mx) : 0.f;
        s_p[tid] = p;
        float sw = p;
#pragma unroll
        for (int off = 16; off > 0; off >>= 1)
            sw += __shfl_xor_sync(0xffffffffu, sw, off);
        if (lane == 0) s_red[wid] = sw;
        __syncthreads();
        if (tid == 0) s_inv = 1.f / (s_red[0] + s_red[1]);
        __syncthreads();

        float inv = s_inv;
        float o = 0.f;
#pragma unroll 10
        for (int m = 0; m < MEM; m++)
            o = fmaf(s_p[m] * inv, cX[m * EMBED + tid], o);
        float nu = s_u[tid] + o;
        __syncthreads();
        s_u[tid] = nu;
        __syncthreads();
    }
    g_u[b * EMBED + tid] = s_u[tid];
}

// ---------------------------------------------------------------------------
// Kernel C: out[32, V] = u[32,64] @ C2[V,64]^T via wmma bf16 hi/lo.
//   D = Ah*Bh + Al*Bh + Ah*Bl   (fp32 acc; dropped Al*Bl <= 2^-18)
// R12 fixes:
//  * A-convert spread over ALL 128 threads (half-row each), not 64.
//  * D staged through smem (store_matrix_sync col-major, ldm=64) and then
//    written to gmem as coalesced float4 runs — replaces the scattered
//    STG.32 pattern of store_matrix_sync(ldm=VOCAB) that made R12 52us.
// Memory-bound target: 25.6MB read + 12.8MB write ~ 10-12us.
// ---------------------------------------------------------------------------
#define GTILE 64
#define LDA   80      // padded stride (elements): 160B rows, 16B-aligned

struct __align__(16) GemmSmem {
    __nv_bfloat16 a_hi[GTILE * LDA];   // 10 KB
    __nv_bfloat16 a_lo[GTILE * LDA];   // 10 KB
    __nv_bfloat16 b_hi[BATCH * LDA];   //  5 KB
    __nv_bfloat16 b_lo[BATCH * LDA];   //  5 KB
    float         d_out[BATCH * GTILE];//  8 KB  [n][m] (col-major stage)
};

__global__ void __launch_bounds__(128) out_gemm_wmma(
        const float* __restrict__ C2, float* __restrict__ out) {
    using namespace nvcuda;
    __shared__ GemmSmem sm;
    int tid = threadIdx.x;
    int v0  = blockIdx.x * GTILE;

    // ---- A convert: 128 threads, each owns half a row (32 elements) ----
    {
        int r  = tid >> 1;             // row 0..63
        int hh = tid & 1;              // half 0..1
        bool valid = (v0 + r) < VOCAB;
        const float4* src = (const float4*)(C2 + (size_t)(v0 + r) * EMBED) + hh * 8;
#pragma unroll
        for (int ch = 0; ch < 4; ch++) {
            float f[8];
            if (valid) {
                float4 f0 = __ldg(src + 2 * ch), f1 = __ldg(src + 2 * ch + 1);
                f[0]=f0.x; f[1]=f0.y; f[2]=f0.z; f[3]=f0.w;
                f[4]=f1.x; f[5]=f1.y; f[6]=f1.z; f[7]=f1.w;
            } else {
#pragma unroll
                for (int i = 0; i < 8; i++) f[i] = 0.f;
            }
            float h[8], l[8];
#pragma unroll
            for (int i = 0; i < 8; i++) {
                h[i] = __bfloat162float(__float2bfloat16_rn(f[i]));
                l[i] = f[i] - h[i];
            }
            uint4 hw = make_uint4(pack_bf16x2(h[0],h[1]), pack_bf16x2(h[2],h[3]),
                                  pack_bf16x2(h[4],h[5]), pack_bf16x2(h[6],h[7]));
            uint4 lw = make_uint4(pack_bf16x2(l[0],l[1]), pack_bf16x2(l[2],l[3]),
                                  pack_bf16x2(l[4],l[5]), pack_bf16x2(l[6],l[7]));
            int col = hh * 32 + ch * 8;
            *(uint4*)&sm.a_hi[r * LDA + col] = hw;
            *(uint4*)&sm.a_lo[r * LDA + col] = lw;
        }
    }
    // ---- B convert: threads 0..63, each owns half a u row ----
    if (tid < 2 * BATCH) {
        int n  = tid >> 1;
        int hh = tid & 1;
        const float4* src = (const float4*)(g_u + n * EMBED) + hh * 8;
#pragma unroll
        for (int ch = 0; ch < 4; ch++) {
            float4 f0 = src[2 * ch], f1 = src[2 * ch + 1];
            float f[8] = {f0.x, f0.y, f0.z, f0.w, f1.x, f1.y, f1.z, f1.w};
            float h[8], l[8];
#pragma unroll
            for (int i = 0; i < 8; i++) {
                h[i] = __bfloat162float(__float2bfloat16_rn(f[i]));
                l[i] = f[i] - h[i];
            }
            uint4 hw = make_uint4(pack_bf16x2(h[0],h[1]), pack_bf16x2(h[2],h[3]),
                                  pack_bf16x2(h[4],h[5]), pack_bf16x2(h[6],h[7]));
            uint4 lw = make_uint4(pack_bf16x2(l[0],l[1]), pack_bf16x2(l[2],l[3]),
                                  pack_bf16x2(l[4],l[5]), pack_bf16x2(l[6],l[7]));
            int col = hh * 32 + ch * 8;
            *(uint4*)&sm.b_hi[n * LDA + col] = hw;
            *(uint4*)&sm.b_lo[n * LDA + col] = lw;
        }
    }
    __syncthreads();

    // ---- wmma: warp w owns m-tile rows [w*16, w*16+16), both n-tiles ----
    int wid = tid >> 5;
    int m0  = wid * 16;

    wmma::fragment<wmma::accumulator, 16, 16, 16, float> d0, d1;
    wmma::fill_fragment(d0, 0.f);
    wmma::fill_fragment(d1, 0.f);
    wmma::fragment<wmma::matrix_a, 16, 16, 16, __nv_bfloat16, wmma::row_major> ah, al;
    wmma::fragment<wmma::matrix_b, 16, 16, 16, __nv_bfloat16, wmma::col_major> bh0, bh1, bl0, bl1;

#pragma unroll
    for (int k = 0; k < 4; k++) {
        wmma::load_matrix_sync(ah,  &sm.a_hi[m0 * LDA + k * 16], LDA);
        wmma::load_matrix_sync(al,  &sm.a_lo[m0 * LDA + k * 16], LDA);
        wmma::load_matrix_sync(bh0, &sm.b_hi[ 0 * LDA + k * 16], LDA);
        wmma::load_matrix_sync(bh1, &sm.b_hi[16 * LDA + k * 16], LDA);
        wmma::load_matrix_sync(bl0, &sm.b_lo[ 0 * LDA + k * 16], LDA);
        wmma::load_matrix_sync(bl1, &sm.b_lo[16 * LDA + k * 16], LDA);
        wmma::mma_sync(d0, ah, bh0, d0);
        wmma::mma_sync(d0, al, bh0, d0);
        wmma::mma_sync(d0, ah, bl0, d0);
        wmma::mma_sync(d1, ah, bh1, d1);
        wmma::mma_sync(d1, al, bh1, d1);
        wmma::mma_sync(d1, ah, bl1, d1);
    }

    // ---- stage D in smem: element (m,n) at d_out[n*64 + m] ----
    wmma::store_matrix_sync(&sm.d_out[m0],              d0, GTILE, wmma::mem_col_major);
    wmma::store_matrix_sync(&sm.d_out[16 * GTILE + m0], d1, GTILE, wmma::mem_col_major);
    __syncthreads();

    // ---- coalesced writeback: float4 runs along vocab dim ----
    // idx -> batch n = idx/16, segment ms = idx%16 (4 floats each).
    // Warp covers 2 full batch rows of 256B contiguous gmem: 4 sectors/warp.
#pragma unroll
    for (int idx = tid; idx < BATCH * (GTILE / 4); idx += 128) {
        int n  = idx >> 4;
        int ms = idx & 15;
        int v  = v0 + ms * 4;
        if (v < VOCAB) {
            float4 val = *(float4*)&sm.d_out[n * GTILE + ms * 4];
            *(float4*)(out + (size_t)n * VOCAB + v) = val;
        }
    }
}

// ---------------------------------------------------------------------------
extern "C" void kernel_launch(void* const* d_in, const int* in_sizes, int n_in,
                              void* d_out, int out_size) {
    const int*   stories = (const int*)d_in[0];
    const int*   queries = (const int*)d_in[1];
    const float* A       = (const float*)d_in[2];
    const float* C       = (const float*)d_in[3];
    const float* enc     = (const float*)d_in[4];
    float*       out     = (float*)d_out;

    context_kernel<<<BATCH * MEM, 256>>>(stories, A, C, enc);
    hops_kernel<<<BATCH, 64>>>(queries, A, enc);
    out_gemm_wmma<<<(VOCAB + GTILE - 1) / GTILE, 128>>>(
        C + (size_t)2 * VOCAB * EMBED, out);
}

// round 17
// speedup vs baseline: 1.4944x; 1.0393x over previous
#include <cuda_runtime.h>
#include <cuda_bf16.h>
#include <mma.h>
#include <cstdint>
#include <math.h>

#define VOCAB   100000
#define EMBED   64
#define SENT    20
#define MEM     50
#define BATCH   32
#define HOPS    3

#define NBLK    296            // 2/SM on 148 SMs; 4-5 fit -> 2.5x residency margin
#define NTHR    128
#define GTILE   64
#define LDA     80             // padded bf16 stride: 160B rows, 16B-aligned
#define NTILES  ((VOCAB + GTILE - 1) / GTILE)   // 1563

// Persistent scratch
__device__ float g_m[4][BATCH * MEM * EMBED];   // mA, mC0, mC1, mC2
__device__ float g_u[BATCH * EMBED];
__device__ float g_scratch[NBLK];               // prefetch sink
__device__ unsigned int g_bcnt[4];              // barrier counters (return to 0)
__device__ unsigned int g_bgen[4];              // barrier generations (monotonic)

struct __align__(16) GemmSmem {
    __nv_bfloat16 a_hi[GTILE * LDA];   // 10 KB
    __nv_bfloat16 a_lo[GTILE * LDA];   // 10 KB
    __nv_bfloat16 b_hi[BATCH * LDA];   //  5 KB
    __nv_bfloat16 b_lo[BATCH * LDA];   //  5 KB
    float         d_out[BATCH * GTILE];//  8 KB
};

__device__ __forceinline__ uint32_t pack_bf16x2(float x, float y) {
    __nv_bfloat162 t = __floats2bfloat162_rn(x, y);
    return *reinterpret_cast<uint32_t*>(&t);
}

// Device-wide sense/generation barrier. 296 blocks vs >=4/SM residency ->
// co-residency has 2.5x margin. Spin bounded at ~0.3s: any logic bug becomes
// a wrong answer (visible), never a container-killing hang.
__device__ __forceinline__ void grid_barrier(int slot) {
    __syncthreads();
    if (threadIdx.x == 0) {
        __threadfence();
        unsigned int my = atomicAdd(&g_bgen[slot], 0u);
        unsigned int a  = atomicAdd(&g_bcnt[slot], 1u);
        if (a == NBLK - 1) {
            g_bcnt[slot] = 0;
            __threadfence();
            atomicAdd(&g_bgen[slot], 1u);     // release
        } else {
            unsigned long spins = 0;
            while (atomicAdd(&g_bgen[slot], 0u) == my) {
                __nanosleep(64);
                if (++spins > (1ul << 22)) break;
            }
        }
    }
    __syncthreads();
}

__global__ void __launch_bounds__(NTHR, 4) mega_kernel(
        const int* __restrict__ stories,
        const int* __restrict__ queries,
        const float* __restrict__ A,
        const float* __restrict__ C,
        const float* __restrict__ enc,
        float* __restrict__ out) {
    using namespace nvcuda;
    __shared__ GemmSmem sm;
    __shared__ float s_u[EMBED];
    __shared__ float s_p[EMBED];
    __shared__ float s_red[2];
    __shared__ float s_inv;

    int tid = threadIdx.x;
    const float* C2 = C + (size_t)2 * VOCAB * EMBED;

    // ================= Phase 1: context gathers =================
    // 6400 units of (bm, table): 64 threads each, 2 units per block pass.
    {
        int e    = tid & 63;
        int half = tid >> 6;
        for (int u = blockIdx.x * 2 + half; u < 4 * BATCH * MEM; u += NBLK * 2) {
            int bm = u >> 2;
            int t  = u & 3;
            const float* tab = (t == 0) ? A : (C + (size_t)(t - 1) * VOCAB * EMBED);
            const int* st = stories + bm * SENT;
            float vals[SENT];
#pragma unroll
            for (int s = 0; s < SENT; s++)
                vals[s] = __ldg(tab + (size_t)__ldg(st + s) * EMBED + e);
            float acc = 0.f;
#pragma unroll
            for (int s = 0; s < SENT; s++)
                acc = fmaf(vals[s], enc[s * EMBED + e], acc);
            g_m[t][bm * EMBED + e] = acc;
        }
    }
    grid_barrier(0);

    // ================= Phase 2: hops (blocks 0..31) + C2 prefetch =========
    if (blockIdx.x < BATCH) {
        int b    = blockIdx.x;
        int lane = tid & 31;
        int wid  = tid >> 5;

        if (tid < EMBED) {
            int qidx[SENT];
#pragma unroll
            for (int s = 0; s < SENT; s++) qidx[s] = queries[b * SENT + s];
            float ue = 0.f;
#pragma unroll
            for (int s = 0; s < SENT; s++)
                ue = fmaf(__ldg(A + (size_t)qidx[s] * EMBED + tid),
                          enc[s * EMBED + tid], ue);
            s_u[tid] = ue;
        }
        __syncthreads();

        for (int hop = 0; hop < HOPS; hop++) {
            const float* mX = g_m[hop]     + b * MEM * EMBED;
            const float* cX = g_m[hop + 1] + b * MEM * EMBED;

            float d = -1e30f;
            if (tid < MEM) {
                float acc = 0.f;
#pragma unroll 16
                for (int e = 0; e < EMBED; e++)
                    acc = fmaf(mX[tid * EMBED + e], s_u[e], acc);
                d = acc;
            }
            float w = d;
#pragma unroll
            for (int off = 16; off > 0; off >>= 1)
                w = fmaxf(w, __shfl_xor_sync(0xffffffffu, w, off));
            if (wid < 2 && lane == 0) s_red[wid] = w;
            __syncthreads();
            float mx = fmaxf(s_red[0], s_red[1]);

            float p = (tid < MEM) ? __expf(d - mx) : 0.f;
            if (tid < EMBED) s_p[tid] = p;
            float sw = p;
#pragma unroll
            for (int off = 16; off > 0; off >>= 1)
                sw += __shfl_xor_sync(0xffffffffu, sw, off);
            if (wid < 2 && lane == 0) s_red[wid] = sw;
            __syncthreads();
            if (tid == 0) s_inv = 1.f / (s_red[0] + s_red[1]);
            __syncthreads();

            if (tid < EMBED) {
                float inv = s_inv;
                float o = 0.f;
#pragma unroll 10
                for (int m = 0; m < MEM; m++)
                    o = fmaf(s_p[m] * inv, cX[m * EMBED + tid], o);
                float nu = s_u[tid] + o;
                __syncthreads();
                s_u[tid] = nu;
            } else {
                __syncthreads();
            }
            __syncthreads();
        }
        if (tid < EMBED) g_u[b * EMBED + tid] = s_u[tid];
    } else {
        // Warm L2 with the head of C2 during the hops window (~6.5 MB).
        const float4* c4 = (const float4*)C2;
        float acc = 0.f;
        int base = (blockIdx.x - BATCH) * NTHR + tid;
#pragma unroll
        for (int i = 0; i < 12; i++) {
            int idx = base + i * (NBLK - BATCH) * NTHR;
            if (idx < VOCAB * EMBED / 4) {
                float4 v = __ldg(c4 + idx);
                acc += v.x + v.y + v.z + v.w;
            }
        }
        g_scratch[blockIdx.x] = acc;   // keep the loads live; deterministic
    }
    grid_barrier(1);

    // ================= Phase 3: out = u @ C2^T (wmma bf16 hi/lo) ==========
    // B (u) convert once per block.
    if (tid < 2 * BATCH) {
        int n  = tid >> 1;
        int hh = tid & 1;
        const float4* src = (const float4*)(g_u + n * EMBED) + hh * 8;
#pragma unroll
        for (int ch = 0; ch < 4; ch++) {
            float4 f0 = src[2 * ch], f1 = src[2 * ch + 1];
            float f[8] = {f0.x, f0.y, f0.z, f0.w, f1.x, f1.y, f1.z, f1.w};
            float h[8], l[8];
#pragma unroll
            for (int i = 0; i < 8; i++) {
                h[i] = __bfloat162float(__float2bfloat16_rn(f[i]));
                l[i] = f[i] - h[i];
            }
            int col = hh * 32 + ch * 8;
            *(uint4*)&sm.b_hi[n * LDA + col] =
                make_uint4(pack_bf16x2(h[0],h[1]), pack_bf16x2(h[2],h[3]),
                           pack_bf16x2(h[4],h[5]), pack_bf16x2(h[6],h[7]));
            *(uint4*)&sm.b_lo[n * LDA + col] =
                make_uint4(pack_bf16x2(l[0],l[1]), pack_bf16x2(l[2],l[3]),
                           pack_bf16x2(l[4],l[5]), pack_bf16x2(l[6],l[7]));
        }
    }
    __syncthreads();

    for (int tile = blockIdx.x; tile < NTILES; tile += NBLK) {
        int v0 = tile * GTILE;

        // A convert: all 128 threads, half a row (32 elems) each.
        {
            int r  = tid >> 1;
            int hh = tid & 1;
            bool valid = (v0 + r) < VOCAB;
            const float4* src = (const float4*)(C2 + (size_t)(v0 + r) * EMBED) + hh * 8;
#pragma unroll
            for (int ch = 0; ch < 4; ch++) {
                float f[8];
                if (valid) {
                    float4 f0 = __ldg(src + 2 * ch), f1 = __ldg(src + 2 * ch + 1);
                    f[0]=f0.x; f[1]=f0.y; f[2]=f0.z; f[3]=f0.w;
                    f[4]=f1.x; f[5]=f1.y; f[6]=f1.z; f[7]=f1.w;
                } else {
#pragma unroll
                    for (int i = 0; i < 8; i++) f[i] = 0.f;
                }
                float h[8], l[8];
#pragma unroll
                for (int i = 0; i < 8; i++) {
                    h[i] = __bfloat162float(__float2bfloat16_rn(f[i]));
                    l[i] = f[i] - h[i];
                }
                int col = hh * 32 + ch * 8;
                *(uint4*)&sm.a_hi[r * LDA + col] =
                    make_uint4(pack_bf16x2(h[0],h[1]), pack_bf16x2(h[2],h[3]),
                               pack_bf16x2(h[4],h[5]), pack_bf16x2(h[6],h[7]));
                *(uint4*)&sm.a_lo[r * LDA + col] =
                    make_uint4(pack_bf16x2(l[0],l[1]), pack_bf16x2(l[2],l[3]),
                               pack_bf16x2(l[4],l[5]), pack_bf16x2(l[6],l[7]));
            }
        }
        __syncthreads();

        // wmma: warp w owns m-rows [w*16, w*16+16), both 16-wide n-tiles.
        {
            int wid = tid >> 5;
            int m0  = wid * 16;
            wmma::fragment<wmma::accumulator, 16, 16, 16, float> d0, d1;
            wmma::fill_fragment(d0, 0.f);
            wmma::fill_fragment(d1, 0.f);
            wmma::fragment<wmma::matrix_a, 16, 16, 16, __nv_bfloat16, wmma::row_major> ah, al;
            wmma::fragment<wmma::matrix_b, 16, 16, 16, __nv_bfloat16, wmma::col_major> bh0, bh1, bl0, bl1;
#pragma unroll
            for (int k = 0; k < 4; k++) {
                wmma::load_matrix_sync(ah,  &sm.a_hi[m0 * LDA + k * 16], LDA);
                wmma::load_matrix_sync(al,  &sm.a_lo[m0 * LDA + k * 16], LDA);
                wmma::load_matrix_sync(bh0, &sm.b_hi[ 0 * LDA + k * 16], LDA);
                wmma::load_matrix_sync(bh1, &sm.b_hi[16 * LDA + k * 16], LDA);
                wmma::load_matrix_sync(bl0, &sm.b_lo[ 0 * LDA + k * 16], LDA);
                wmma::load_matrix_sync(bl1, &sm.b_lo[16 * LDA + k * 16], LDA);
                wmma::mma_sync(d0, ah, bh0, d0);
                wmma::mma_sync(d0, al, bh0, d0);
                wmma::mma_sync(d0, ah, bl0, d0);
                wmma::mma_sync(d1, ah, bh1, d1);
                wmma::mma_sync(d1, al, bh1, d1);
                wmma::mma_sync(d1, ah, bl1, d1);
            }
            wmma::store_matrix_sync(&sm.d_out[m0],              d0, GTILE, wmma::mem_col_major);
            wmma::store_matrix_sync(&sm.d_out[16 * GTILE + m0], d1, GTILE, wmma::mem_col_major);
        }
        __syncthreads();

        // Coalesced writeback: warp = 2 batch rows x 256B contiguous.
#pragma unroll
        for (int idx = tid; idx < BATCH * (GTILE / 4); idx += NTHR) {
            int n  = idx >> 4;
            int ms = idx & 15;
            int v  = v0 + ms * 4;
            if (v < VOCAB)
                *(float4*)(out + (size_t)n * VOCAB + v) = *(float4*)&sm.d_out[n * GTILE + ms * 4];
        }
        __syncthreads();   // d_out / a tiles reused next iteration
    }
}

// ---------------------------------------------------------------------------
extern "C" void kernel_launch(void* const* d_in, const int* in_sizes, int n_in,
                              void* d_out, int out_size) {
    const int*   stories = (const int*)d_in[0];
    const int*   queries = (const int*)d_in[1];
    const float* A       = (const float*)d_in[2];
    const float* C       = (const float*)d_in[3];
    const float* enc     = (const float*)d_in[4];
    float*       out     = (float*)d_out;

    mega_kernel<<<NBLK, NTHR>>>(stories, queries, A, C, enc, out);
}